// round 1
// baseline (speedup 1.0000x reference)
#include <cuda_runtime.h>
#include <cstddef>

typedef unsigned long long ull;

#define D32 32
#define NMAX 50000
#define EMAX 800000
#define BMAX 16

// ---------------- scratch (device globals; no allocation allowed) ----------------
__device__ float g_PQ[(size_t)NMAX * 128];   // per-node P (64) | Q (64)
__device__ float g_R[BMAX * 64];             // per-graph u@W1d + b1
__device__ float g_agg[(size_t)NMAX * 32];   // scatter-sum of e -> dst
__device__ float g_xg[BMAX * 32];            // scatter-sum of x -> batch
__device__ float g_invdeg[NMAX];
__device__ float g_invgc[BMAX];
__device__ int   g_deg[NMAX];
__device__ int   g_gcnt[BMAX];

// ---------------- packed f32x2 helpers ----------------
__device__ __forceinline__ ull pk2(float x) {
    ull r; asm("mov.b64 %0, {%1, %1};" : "=l"(r) : "f"(x)); return r;
}
__device__ __forceinline__ ull pk(float lo, float hi) {
    ull r; asm("mov.b64 %0, {%1, %2};" : "=l"(r) : "f"(lo), "f"(hi)); return r;
}
__device__ __forceinline__ void upk(ull v, float& lo, float& hi) {
    asm("mov.b64 {%0, %1}, %2;" : "=f"(lo), "=f"(hi) : "l"(v));
}
__device__ __forceinline__ void ffma2(ull& acc, ull a, ull b) {
    asm("fma.rn.f32x2 %0, %1, %2, %0;" : "+l"(acc) : "l"(a), "l"(b));
}
__device__ __forceinline__ ull fadd2(ull a, ull b) {
    ull r; asm("add.rn.f32x2 %0, %1, %2;" : "=l"(r) : "l"(a), "l"(b)); return r;
}

// acc h[32] (=64 floats packed) += ev * wrow[0..63]
__device__ __forceinline__ void mac_row64(ull h[32], float ev, const float* wrow) {
    ull ek = pk2(ev);
    const ulonglong2* w = (const ulonglong2*)wrow;
#pragma unroll
    for (int j = 0; j < 16; j++) {
        ulonglong2 ww = w[j];
        ffma2(h[2 * j], ek, ww.x);
        ffma2(h[2 * j + 1], ek, ww.y);
    }
}
// acc o[16] (=32 floats packed) += ev * wrow[0..31]
__device__ __forceinline__ void mac_row32(ull o[16], float ev, const float* wrow) {
    ull ek = pk2(ev);
    const ulonglong2* w = (const ulonglong2*)wrow;
#pragma unroll
    for (int j = 0; j < 8; j++) {
        ulonglong2 ww = w[j];
        ffma2(o[2 * j], ek, ww.x);
        ffma2(o[2 * j + 1], ek, ww.y);
    }
}
__device__ __forceinline__ void red_add_v4(float* gptr, float a, float b, float c, float d) {
    size_t ga = __cvta_generic_to_global(gptr);
    asm volatile("red.global.add.v4.f32 [%0], {%1, %2, %3, %4};"
                 :: "l"(ga), "f"(a), "f"(b), "f"(c), "f"(d) : "memory");
}

// ---------------- simple kernels ----------------
__global__ void k_count(const int* __restrict__ idx, int* __restrict__ cnt, int n) {
    int i = blockIdx.x * blockDim.x + threadIdx.x;
    if (i < n) atomicAdd(&cnt[idx[i]], 1);
}

__global__ void k_inv(const int* __restrict__ deg, float* __restrict__ invdeg, int N,
                      const int* __restrict__ gcnt, float* __restrict__ invgc, int B) {
    int i = blockIdx.x * blockDim.x + threadIdx.x;
    if (i < N) invdeg[i] = 1.0f / fmaxf((float)deg[i], 1.0f);
    if (i < B) invgc[i] = 1.0f / fmaxf((float)gcnt[i], 1.0f);
}

// eval-mode batchnorm, vectorized float4 (rows of 32 floats = 8 float4)
__global__ void k_bn(const float4* __restrict__ in, float4* __restrict__ out,
                     const float* __restrict__ gamma, const float* __restrict__ beta, int n4) {
    int i = blockIdx.x * blockDim.x + threadIdx.x;
    if (i >= n4) return;
    const float s = rsqrtf(1.0f + 1e-5f);
    int c = (i & 7) * 4;
    float4 v = in[i];
    float4 o;
    o.x = v.x * (gamma[c + 0] * s) + beta[c + 0];
    o.y = v.y * (gamma[c + 1] * s) + beta[c + 1];
    o.z = v.z * (gamma[c + 2] * s) + beta[c + 2];
    o.w = v.w * (gamma[c + 3] * s) + beta[c + 3];
    out[i] = o;
}

// P = x @ W1[0:32], Q = x @ W1[32:64]   (one thread per (node, col))
__global__ void k_pq(const float* __restrict__ x, const float* __restrict__ W1,
                     float* __restrict__ PQ, int N) {
    __shared__ __align__(16) float sW[64 * 64];
    for (int i = threadIdx.x; i < 4096; i += blockDim.x) sW[i] = W1[i];
    __syncthreads();
    int t = blockIdx.x * blockDim.x + threadIdx.x;
    int n = t >> 6, j = t & 63;
    if (n >= N) return;
    float xr[32];
    const float4* xp = (const float4*)(x + (size_t)n * 32);
#pragma unroll
    for (int kk = 0; kk < 8; kk++) {
        float4 v = xp[kk];
        xr[4 * kk] = v.x; xr[4 * kk + 1] = v.y; xr[4 * kk + 2] = v.z; xr[4 * kk + 3] = v.w;
    }
    float p = 0.f, q = 0.f;
#pragma unroll
    for (int k = 0; k < 32; k++) {
        p += xr[k] * sW[k * 64 + j];
        q += xr[k] * sW[(k + 32) * 64 + j];
    }
    PQ[(size_t)n * 128 + j] = p;
    PQ[(size_t)n * 128 + 64 + j] = q;
}

// R[b][j] = b1[j] + sum_k u[b][k] * W1[96+k][j]   (single block, 1024 threads)
__global__ void k_r(const float* __restrict__ u, const float* __restrict__ W1,
                    const float* __restrict__ b1, float* __restrict__ R, int B) {
    int t = threadIdx.x;
    int b = t >> 6, j = t & 63;
    if (b >= B) return;
    float acc = b1[j];
#pragma unroll
    for (int k = 0; k < 32; k++) acc += u[b * 32 + k] * W1[(96 + k) * 64 + j];
    R[b * 64 + j] = acc;
}

// Edge model: e_new = relu(P[src]+Q[dst]+R[batch[src]] + e@W1c) @ W2 + b2
// Fused: scatter-sum e_new into agg[dst].
__global__ __launch_bounds__(128) void k_edge(
    const float* __restrict__ PQ, const float* __restrict__ R,
    const int* __restrict__ ei, const int* __restrict__ batch,
    float* __restrict__ e, float* __restrict__ agg,
    const float* __restrict__ W1c, const float* __restrict__ W2,
    const float* __restrict__ b2, int E) {
    __shared__ __align__(16) float sW1[32 * 64];
    __shared__ __align__(16) float sW2[64 * 32];
    __shared__ __align__(16) float sB2[32];
    for (int i = threadIdx.x; i < 2048; i += 128) { sW1[i] = W1c[i]; sW2[i] = W2[i]; }
    if (threadIdx.x < 32) sB2[threadIdx.x] = b2[threadIdx.x];
    __syncthreads();

    int i = blockIdx.x * blockDim.x + threadIdx.x;
    if (i >= E) return;
    int src = ei[i], dst = ei[E + i];
    int b = batch[src];

    ull h[32];
    const ulonglong2* Pp = (const ulonglong2*)(PQ + (size_t)src * 128);
    const ulonglong2* Qp = (const ulonglong2*)(PQ + (size_t)dst * 128 + 64);
    const ulonglong2* Rp = (const ulonglong2*)(R + b * 64);
#pragma unroll
    for (int j = 0; j < 16; j++) {
        ulonglong2 pp = Pp[j], qq = Qp[j], rr = Rp[j];
        h[2 * j]     = fadd2(fadd2(pp.x, qq.x), rr.x);
        h[2 * j + 1] = fadd2(fadd2(pp.y, qq.y), rr.y);
    }
    const float4* ep = (const float4*)(e + (size_t)i * 32);
#pragma unroll
    for (int kk = 0; kk < 8; kk++) {
        float4 v = ep[kk];
        mac_row64(h, v.x, sW1 + (4 * kk + 0) * 64);
        mac_row64(h, v.y, sW1 + (4 * kk + 1) * 64);
        mac_row64(h, v.z, sW1 + (4 * kk + 2) * 64);
        mac_row64(h, v.w, sW1 + (4 * kk + 3) * 64);
    }
#pragma unroll
    for (int j = 0; j < 32; j++) {
        float lo, hi; upk(h[j], lo, hi);
        h[j] = pk(fmaxf(lo, 0.f), fmaxf(hi, 0.f));
    }
    ull o[16];
    const ulonglong2* bb = (const ulonglong2*)sB2;
#pragma unroll
    for (int j = 0; j < 8; j++) { ulonglong2 t = bb[j]; o[2 * j] = t.x; o[2 * j + 1] = t.y; }
#pragma unroll
    for (int kp = 0; kp < 32; kp++) {
        float lo, hi; upk(h[kp], lo, hi);
        mac_row32(o, lo, sW2 + (2 * kp) * 32);
        mac_row32(o, hi, sW2 + (2 * kp + 1) * 32);
    }
    float f[32];
#pragma unroll
    for (int j = 0; j < 16; j++) upk(o[j], f[2 * j], f[2 * j + 1]);

    float4* eo = (float4*)(e + (size_t)i * 32);
#pragma unroll
    for (int c = 0; c < 8; c++) eo[c] = make_float4(f[4 * c], f[4 * c + 1], f[4 * c + 2], f[4 * c + 3]);
    float* ag = agg + (size_t)dst * 32;
#pragma unroll
    for (int c = 0; c < 8; c++) red_add_v4(ag + 4 * c, f[4 * c], f[4 * c + 1], f[4 * c + 2], f[4 * c + 3]);
}

// Node model: x_new = relu([x, agg*invdeg, u[batch]] @ W1 + b1) @ W2 + b2
// Fused: scatter-sum x_new into xg[batch].
__global__ __launch_bounds__(128) void k_node(
    float* __restrict__ x, const float* __restrict__ agg, const float* __restrict__ invdeg,
    const float* __restrict__ u, const int* __restrict__ batch, float* __restrict__ xg,
    const float* __restrict__ W1, const float* __restrict__ b1,
    const float* __restrict__ W2, const float* __restrict__ b2, int N) {
    __shared__ __align__(16) float sW1[96 * 64];
    __shared__ __align__(16) float sW2[64 * 32];
    __shared__ __align__(16) float sB1[64];
    __shared__ __align__(16) float sB2[32];
    for (int i = threadIdx.x; i < 6144; i += 128) sW1[i] = W1[i];
    for (int i = threadIdx.x; i < 2048; i += 128) sW2[i] = W2[i];
    if (threadIdx.x < 64) sB1[threadIdx.x] = b1[threadIdx.x];
    if (threadIdx.x < 32) sB2[threadIdx.x] = b2[threadIdx.x];
    __syncthreads();

    int n = blockIdx.x * blockDim.x + threadIdx.x;
    if (n >= N) return;

    ull h[32];
    const ulonglong2* bb1 = (const ulonglong2*)sB1;
#pragma unroll
    for (int j = 0; j < 16; j++) { ulonglong2 t = bb1[j]; h[2 * j] = t.x; h[2 * j + 1] = t.y; }

    const float4* xp = (const float4*)(x + (size_t)n * 32);
#pragma unroll
    for (int kk = 0; kk < 8; kk++) {
        float4 v = xp[kk];
        mac_row64(h, v.x, sW1 + (4 * kk + 0) * 64);
        mac_row64(h, v.y, sW1 + (4 * kk + 1) * 64);
        mac_row64(h, v.z, sW1 + (4 * kk + 2) * 64);
        mac_row64(h, v.w, sW1 + (4 * kk + 3) * 64);
    }
    float idg = invdeg[n];
    const float4* ap = (const float4*)(agg + (size_t)n * 32);
#pragma unroll
    for (int kk = 0; kk < 8; kk++) {
        float4 v = ap[kk];
        mac_row64(h, v.x * idg, sW1 + (32 + 4 * kk + 0) * 64);
        mac_row64(h, v.y * idg, sW1 + (32 + 4 * kk + 1) * 64);
        mac_row64(h, v.z * idg, sW1 + (32 + 4 * kk + 2) * 64);
        mac_row64(h, v.w * idg, sW1 + (32 + 4 * kk + 3) * 64);
    }
    int b = batch[n];
    const float4* up = (const float4*)(u + (size_t)b * 32);
#pragma unroll
    for (int kk = 0; kk < 8; kk++) {
        float4 v = up[kk];
        mac_row64(h, v.x, sW1 + (64 + 4 * kk + 0) * 64);
        mac_row64(h, v.y, sW1 + (64 + 4 * kk + 1) * 64);
        mac_row64(h, v.z, sW1 + (64 + 4 * kk + 2) * 64);
        mac_row64(h, v.w, sW1 + (64 + 4 * kk + 3) * 64);
    }
#pragma unroll
    for (int j = 0; j < 32; j++) {
        float lo, hi; upk(h[j], lo, hi);
        h[j] = pk(fmaxf(lo, 0.f), fmaxf(hi, 0.f));
    }
    ull o[16];
    const ulonglong2* bb2 = (const ulonglong2*)sB2;
#pragma unroll
    for (int j = 0; j < 8; j++) { ulonglong2 t = bb2[j]; o[2 * j] = t.x; o[2 * j + 1] = t.y; }
#pragma unroll
    for (int kp = 0; kp < 32; kp++) {
        float lo, hi; upk(h[kp], lo, hi);
        mac_row32(o, lo, sW2 + (2 * kp) * 32);
        mac_row32(o, hi, sW2 + (2 * kp + 1) * 32);
    }
    float f[32];
#pragma unroll
    for (int j = 0; j < 16; j++) upk(o[j], f[2 * j], f[2 * j + 1]);

    float4* xo = (float4*)(x + (size_t)n * 32);
#pragma unroll
    for (int c = 0; c < 8; c++) xo[c] = make_float4(f[4 * c], f[4 * c + 1], f[4 * c + 2], f[4 * c + 3]);
    float* gp = xg + (size_t)b * 32;
#pragma unroll
    for (int c = 0; c < 8; c++) red_add_v4(gp + 4 * c, f[4 * c], f[4 * c + 1], f[4 * c + 2], f[4 * c + 3]);
}

// Global model: u_new = relu([u, xg*invgc] @ W1 + b1) @ W2 + b2   (1 block)
__global__ void k_glob(float* __restrict__ u, const float* __restrict__ xg,
                       const float* __restrict__ invgc,
                       const float* __restrict__ W1, const float* __restrict__ b1,
                       const float* __restrict__ W2, const float* __restrict__ b2, int B) {
    __shared__ float sh[BMAX * 64];
    int t = threadIdx.x;
    {
        int b = t >> 6, j = t & 63;
        if (b < B) {
            float acc = b1[j];
            float ig = invgc[b];
#pragma unroll
            for (int k = 0; k < 32; k++) acc += u[b * 32 + k] * W1[k * 64 + j];
#pragma unroll
            for (int k = 0; k < 32; k++) acc += xg[b * 32 + k] * ig * W1[(32 + k) * 64 + j];
            sh[b * 64 + j] = fmaxf(acc, 0.f);
        }
    }
    __syncthreads();
    {
        int b = t >> 5, jo = t & 31;
        if (t < B * 32) {
            float acc = b2[jo];
#pragma unroll
            for (int k = 0; k < 64; k++) acc += sh[b * 64 + k] * W2[k * 32 + jo];
            u[b * 32 + jo] = acc;
        }
    }
}

// ---------------- launch ----------------
extern "C" void kernel_launch(void* const* d_in, const int* in_sizes, int n_in,
                              void* d_out, int out_size) {
    const float* node_feats = (const float*)d_in[0];
    const int*   edge_index = (const int*)d_in[1];
    const float* edge_feats = (const float*)d_in[2];
    const float* glob_feats = (const float*)d_in[3];
    const int*   batch      = (const int*)d_in[4];
    const float* node_gamma = (const float*)d_in[5];
    const float* node_beta  = (const float*)d_in[6];
    const float* edge_gamma = (const float*)d_in[7];
    const float* edge_beta  = (const float*)d_in[8];
    const float* glob_gamma = (const float*)d_in[9];
    const float* glob_beta  = (const float*)d_in[10];
    const float* edge_W1 = (const float*)d_in[11];
    const float* edge_b1 = (const float*)d_in[12];
    const float* edge_W2 = (const float*)d_in[13];
    const float* edge_b2 = (const float*)d_in[14];
    const float* node_W1 = (const float*)d_in[15];
    const float* node_b1 = (const float*)d_in[16];
    const float* node_W2 = (const float*)d_in[17];
    const float* node_b2 = (const float*)d_in[18];
    const float* glob_W1 = (const float*)d_in[19];
    const float* glob_b1 = (const float*)d_in[20];
    const float* glob_W2 = (const float*)d_in[21];
    const float* glob_b2 = (const float*)d_in[22];

    const int N = in_sizes[0] / D32;
    const int E = in_sizes[2] / D32;
    const int B = in_sizes[3] / D32;

    float* x = (float*)d_out;                  // [N,32]
    float* e = x + (size_t)N * D32;            // [E,32]
    float* u = e + (size_t)E * D32;            // [B,32]

    void *pPQ, *pR, *pAgg, *pXg, *pInvdeg, *pInvgc, *pDeg, *pGcnt;
    cudaGetSymbolAddress(&pPQ, g_PQ);
    cudaGetSymbolAddress(&pR, g_R);
    cudaGetSymbolAddress(&pAgg, g_agg);
    cudaGetSymbolAddress(&pXg, g_xg);
    cudaGetSymbolAddress(&pInvdeg, g_invdeg);
    cudaGetSymbolAddress(&pInvgc, g_invgc);
    cudaGetSymbolAddress(&pDeg, g_deg);
    cudaGetSymbolAddress(&pGcnt, g_gcnt);

    // degree / graph-count denominators (fixed index structure)
    cudaMemsetAsync(pDeg, 0, (size_t)N * sizeof(int));
    cudaMemsetAsync(pGcnt, 0, (size_t)B * sizeof(int));
    k_count<<<(E + 255) / 256, 256>>>(edge_index + E, (int*)pDeg, E);
    k_count<<<(N + 255) / 256, 256>>>(batch, (int*)pGcnt, N);
    k_inv<<<(N + 255) / 256, 256>>>((const int*)pDeg, (float*)pInvdeg, N,
                                    (const int*)pGcnt, (float*)pInvgc, B);

    // input batchnorms -> working buffers inside d_out
    k_bn<<<(N * 8 + 255) / 256, 256>>>((const float4*)node_feats, (float4*)x, node_gamma, node_beta, N * 8);
    k_bn<<<(E * 8 + 255) / 256, 256>>>((const float4*)edge_feats, (float4*)e, edge_gamma, edge_beta, E * 8);
    k_bn<<<(B * 8 + 255) / 256, 256>>>((const float4*)glob_feats, (float4*)u, glob_gamma, glob_beta, B * 8);

    for (int l = 0; l < 3; l++) {
        cudaMemsetAsync(pAgg, 0, (size_t)N * D32 * sizeof(float));
        cudaMemsetAsync(pXg, 0, (size_t)B * D32 * sizeof(float));

        const float* eW1 = edge_W1 + (size_t)l * 128 * 64;
        k_pq<<<(N + 3) / 4, 256>>>(x, eW1, (float*)pPQ, N);
        k_r<<<1, 1024>>>(u, eW1, edge_b1 + l * 64, (float*)pR, B);
        k_edge<<<(E + 127) / 128, 128>>>((const float*)pPQ, (const float*)pR,
                                         edge_index, batch, e, (float*)pAgg,
                                         eW1 + 64 * 64, edge_W2 + (size_t)l * 2048,
                                         edge_b2 + l * 32, E);
        k_node<<<(N + 127) / 128, 128>>>(x, (const float*)pAgg, (const float*)pInvdeg,
                                         u, batch, (float*)pXg,
                                         node_W1 + (size_t)l * 6144, node_b1 + l * 64,
                                         node_W2 + (size_t)l * 2048, node_b2 + l * 32, N);
        k_glob<<<1, 1024>>>(u, (const float*)pXg, (const float*)pInvgc,
                            glob_W1 + (size_t)l * 4096, glob_b1 + l * 64,
                            glob_W2 + (size_t)l * 2048, glob_b2 + l * 32, B);
    }
}

// round 3
// speedup vs baseline: 1.0144x; 1.0144x over previous
#include <cuda_runtime.h>
#include <cstddef>

typedef unsigned long long ull;

#define D32 32
#define NMAX 50000
#define BMAX 16

__device__ float g_PQ[(size_t)NMAX * 128];
__device__ float g_R[BMAX * 64];
__device__ float g_agg[(size_t)NMAX * 32];
__device__ float g_xg[BMAX * 32];
__device__ float g_invdeg[NMAX];
__device__ float g_invgc[BMAX];
__device__ int   g_deg[NMAX];
__device__ int   g_gcnt[BMAX];

__device__ __forceinline__ ull pk2(float x) {
    ull r; asm("mov.b64 %0, {%1, %1};" : "=l"(r) : "f"(x)); return r;
}
__device__ __forceinline__ ull pk(float lo, float hi) {
    ull r; asm("mov.b64 %0, {%1, %2};" : "=l"(r) : "f"(lo), "f"(hi)); return r;
}
__device__ __forceinline__ void upk(ull v, float& lo, float& hi) {
    asm("mov.b64 {%0, %1}, %2;" : "=f"(lo), "=f"(hi) : "l"(v));
}
__device__ __forceinline__ void ffma2(ull& acc, ull a, ull b) {
    asm("fma.rn.f32x2 %0, %1, %2, %0;" : "+l"(acc) : "l"(a), "l"(b));
}
__device__ __forceinline__ ull fadd2(ull a, ull b) {
    ull r; asm("add.rn.f32x2 %0, %1, %2;" : "=l"(r) : "l"(a), "l"(b)); return r;
}
__device__ __forceinline__ void mac_row64(ull h[32], float ev, const float* wrow) {
    ull ek = pk2(ev);
    const ulonglong2* w = (const ulonglong2*)wrow;
#pragma unroll
    for (int j = 0; j < 16; j++) {
        ulonglong2 ww = w[j];
        ffma2(h[2 * j], ek, ww.x);
        ffma2(h[2 * j + 1], ek, ww.y);
    }
}
__device__ __forceinline__ void mac_row32(ull o[16], float ev, const float* wrow) {
    ull ek = pk2(ev);
    const ulonglong2* w = (const ulonglong2*)wrow;
#pragma unroll
    for (int j = 0; j < 8; j++) {
        ulonglong2 ww = w[j];
        ffma2(o[2 * j], ek, ww.x);
        ffma2(o[2 * j + 1], ek, ww.y);
    }
}
__device__ __forceinline__ void red_add_v4(float* gptr, float a, float b, float c, float d) {
    size_t ga = __cvta_generic_to_global(gptr);
    asm volatile("red.global.add.v4.f32 [%0], {%1, %2, %3, %4};"
                 :: "l"(ga), "f"(a), "f"(b), "f"(c), "f"(d) : "memory");
}

// ---------------- small kernels ----------------
__global__ void k_count(const int* __restrict__ idx, int* __restrict__ cnt, int n) {
    int i = blockIdx.x * blockDim.x + threadIdx.x;
    if (i < n) atomicAdd(&cnt[idx[i]], 1);
}
__global__ void k_inv(const int* __restrict__ deg, float* __restrict__ invdeg, int N,
                      const int* __restrict__ gcnt, float* __restrict__ invgc, int B) {
    int i = blockIdx.x * blockDim.x + threadIdx.x;
    if (i < N) invdeg[i] = 1.0f / fmaxf((float)deg[i], 1.0f);
    if (i < B) invgc[i] = 1.0f / fmaxf((float)gcnt[i], 1.0f);
}
// BN + optional zeroing of a count array (avoids separate memset launches)
__global__ void k_bn(const float4* __restrict__ in, float4* __restrict__ out,
                     const float* __restrict__ gamma, const float* __restrict__ beta,
                     int n4, int* __restrict__ zcnt, int zn) {
    int i = blockIdx.x * blockDim.x + threadIdx.x;
    if (zcnt && i < zn) zcnt[i] = 0;
    if (i >= n4) return;
    const float s = rsqrtf(1.0f + 1e-5f);
    int c = (i & 7) * 4;
    float4 v = in[i];
    float4 o;
    o.x = v.x * (gamma[c + 0] * s) + beta[c + 0];
    o.y = v.y * (gamma[c + 1] * s) + beta[c + 1];
    o.z = v.z * (gamma[c + 2] * s) + beta[c + 2];
    o.w = v.w * (gamma[c + 3] * s) + beta[c + 3];
    out[i] = o;
}

// P|Q = x @ W1[0:64]; also zeroes agg (needed before k_edge2)
__global__ void k_pq(const float* __restrict__ x, const float* __restrict__ W1,
                     float* __restrict__ PQ, float* __restrict__ agg, int N) {
    __shared__ __align__(16) float sW[64 * 64];
    for (int i = threadIdx.x; i < 4096; i += blockDim.x) sW[i] = W1[i];
    __syncthreads();
    int t = blockIdx.x * blockDim.x + threadIdx.x;
    int n = t >> 6, j = t & 63;
    if (n >= N) return;
    if (j < 32) agg[(size_t)n * 32 + j] = 0.0f;
    float xr[32];
    const float4* xp = (const float4*)(x + (size_t)n * 32);
#pragma unroll
    for (int kk = 0; kk < 8; kk++) {
        float4 v = xp[kk];
        xr[4 * kk] = v.x; xr[4 * kk + 1] = v.y; xr[4 * kk + 2] = v.z; xr[4 * kk + 3] = v.w;
    }
    float p = 0.f, q = 0.f;
#pragma unroll
    for (int k = 0; k < 32; k++) {
        p += xr[k] * sW[k * 64 + j];
        q += xr[k] * sW[(k + 32) * 64 + j];
    }
    PQ[(size_t)n * 128 + j] = p;
    PQ[(size_t)n * 128 + 64 + j] = q;
}

// R[b][j] = b1[j] + u[b] @ W1[96:128]; also zeroes xg
__global__ void k_r(const float* __restrict__ u, const float* __restrict__ W1,
                    const float* __restrict__ b1, float* __restrict__ R,
                    float* __restrict__ xg, int B) {
    int t = threadIdx.x;
    if (t < B * 32) xg[t] = 0.0f;
    int b = t >> 6, j = t & 63;
    if (b >= B) return;
    float acc = b1[j];
#pragma unroll
    for (int k = 0; k < 32; k++) acc += u[b * 32 + k] * W1[(96 + k) * 64 + j];
    R[b * 64 + j] = acc;
}

// ============ paired edge kernel ============
// 128 threads / 128 edges per block. Thread t: pair le0 = t&~1, half s = t&1.
// Computes hidden cols [32s,32s+32) for BOTH edges; GEMM2 half-k partials
// exchanged with partner lane (t^1) through smem.
__global__ __launch_bounds__(128) void k_edge2(
    const float* __restrict__ PQ, const float* __restrict__ R,
    const int* __restrict__ ei, const int* __restrict__ batch,
    const float* __restrict__ e_in, float* __restrict__ e_out,
    float* __restrict__ agg,
    const float* __restrict__ W1c, const float* __restrict__ W2,
    const float* __restrict__ b2,
    const float* __restrict__ bng, const float* __restrict__ bnb, int use_bn,
    int E)
{
    __shared__ float se[128 * 33];                 // staged e rows / exchange buf
    __shared__ __align__(16) float sW1[32 * 72];   // row k at k*72, half s at +s*36
    __shared__ __align__(16) float sW2[2056];      // row k at k*32 + (k>=32)*8
    __shared__ float sB2[32];

    int t = threadIdx.x;
    for (int i = t; i < 2048; i += 128) {
        int k1 = i >> 6, j1 = i & 63;
        sW1[k1 * 72 + (j1 >> 5) * 36 + (j1 & 31)] = W1c[i];
        int k2 = i >> 5, j2 = i & 31;
        sW2[k2 * 32 + (k2 >= 32 ? 8 : 0) + j2] = W2[i];
    }
    if (t < 32) sB2[t] = b2[t];

    int ge = blockIdx.x * 128 + t;
    if (ge < E) {
        const float4* srcp = (const float4*)(e_in + (size_t)ge * 32);
        const float rs = rsqrtf(1.0f + 1e-5f);
#pragma unroll
        for (int c = 0; c < 8; c++) {
            float4 v = srcp[c];
            if (use_bn) {
                v.x = v.x * (bng[4 * c + 0] * rs) + bnb[4 * c + 0];
                v.y = v.y * (bng[4 * c + 1] * rs) + bnb[4 * c + 1];
                v.z = v.z * (bng[4 * c + 2] * rs) + bnb[4 * c + 2];
                v.w = v.w * (bng[4 * c + 3] * rs) + bnb[4 * c + 3];
            }
            se[t * 33 + 4 * c + 0] = v.x;
            se[t * 33 + 4 * c + 1] = v.y;
            se[t * 33 + 4 * c + 2] = v.z;
            se[t * 33 + 4 * c + 3] = v.w;
        }
    }

    const int s = t & 1;
    const int le0 = t & ~1;
    const int e0 = blockIdx.x * 128 + le0;
    const int e1 = e0 + 1;
    int src0 = (e0 < E) ? ei[e0] : 0;
    int dst0 = (e0 < E) ? ei[E + e0] : 0;
    int src1 = (e1 < E) ? ei[e1] : 0;
    int dst1 = (e1 < E) ? ei[E + e1] : 0;
    int b0 = batch[src0], b1i = batch[src1];

    ull h0[16], h1[16];
    {
        const ulonglong2* P0 = (const ulonglong2*)(PQ + (size_t)src0 * 128 + s * 32);
        const ulonglong2* Q0 = (const ulonglong2*)(PQ + (size_t)dst0 * 128 + 64 + s * 32);
        const ulonglong2* R0 = (const ulonglong2*)(R + b0 * 64 + s * 32);
        const ulonglong2* P1 = (const ulonglong2*)(PQ + (size_t)src1 * 128 + s * 32);
        const ulonglong2* Q1 = (const ulonglong2*)(PQ + (size_t)dst1 * 128 + 64 + s * 32);
        const ulonglong2* R1 = (const ulonglong2*)(R + b1i * 64 + s * 32);
#pragma unroll
        for (int c = 0; c < 8; c++) {
            ulonglong2 pp = P0[c], qq = Q0[c], rr = R0[c];
            h0[2 * c]     = fadd2(fadd2(pp.x, qq.x), rr.x);
            h0[2 * c + 1] = fadd2(fadd2(pp.y, qq.y), rr.y);
            ulonglong2 p2 = P1[c], q2 = Q1[c], r2 = R1[c];
            h1[2 * c]     = fadd2(fadd2(p2.x, q2.x), r2.x);
            h1[2 * c + 1] = fadd2(fadd2(p2.y, q2.y), r2.y);
        }
    }
    __syncthreads();

    // GEMM1: h += e @ W1c (our 32-col half, both edges share weight fragment)
#pragma unroll 8
    for (int k = 0; k < 32; k++) {
        ull a0 = pk2(se[le0 * 33 + k]);
        ull a1 = pk2(se[(le0 + 1) * 33 + k]);
        const ulonglong2* w = (const ulonglong2*)&sW1[k * 72 + s * 36];
#pragma unroll
        for (int c = 0; c < 8; c++) {
            ulonglong2 ww = w[c];
            ffma2(h0[2 * c], a0, ww.x); ffma2(h0[2 * c + 1], a0, ww.y);
            ffma2(h1[2 * c], a1, ww.x); ffma2(h1[2 * c + 1], a1, ww.y);
        }
    }
#pragma unroll
    for (int j = 0; j < 16; j++) {
        float lo, hi;
        upk(h0[j], lo, hi); h0[j] = pk(fmaxf(lo, 0.f), fmaxf(hi, 0.f));
        upk(h1[j], lo, hi); h1[j] = pk(fmaxf(lo, 0.f), fmaxf(hi, 0.f));
    }

    // GEMM2 partials over k-slice [32s, 32s+32)
    ull o0[16], o1[16];
#pragma unroll
    for (int j = 0; j < 16; j++) { o0[j] = 0ull; o1[j] = 0ull; }
#pragma unroll 4
    for (int ku = 0; ku < 16; ku++) {
        float a0lo, a0hi, a1lo, a1hi;
        upk(h0[ku], a0lo, a0hi);
        upk(h1[ku], a1lo, a1hi);
        int base = (32 * s + 2 * ku) * 32 + s * 8;
        const ulonglong2* wa = (const ulonglong2*)&sW2[base];
        const ulonglong2* wb = (const ulonglong2*)&sW2[base + 32];
        ull ka0 = pk2(a0lo), ka1 = pk2(a0hi), kb0 = pk2(a1lo), kb1 = pk2(a1hi);
#pragma unroll
        for (int c = 0; c < 8; c++) {
            ulonglong2 w0 = wa[c];
            ulonglong2 w1 = wb[c];
            ffma2(o0[2 * c], ka0, w0.x); ffma2(o0[2 * c + 1], ka0, w0.y);
            ffma2(o0[2 * c], ka1, w1.x); ffma2(o0[2 * c + 1], ka1, w1.y);
            ffma2(o1[2 * c], kb0, w0.x); ffma2(o1[2 * c + 1], kb0, w0.y);
            ffma2(o1[2 * c], kb1, w1.x); ffma2(o1[2 * c + 1], kb1, w1.y);
        }
    }

    // exchange partials with partner lane through se (protected by block sync)
    __syncthreads();
    {
        float* slot = &se[(t ^ 1) * 33];
        ull* oth = s ? o0 : o1;     // partial the PARTNER needs (its edge, my k-slice)
#pragma unroll
        for (int j = 0; j < 16; j++) {
            float lo, hi; upk(oth[j], lo, hi);
            slot[2 * j] = lo; slot[2 * j + 1] = hi;
        }
    }
    __syncwarp();
    {
        const float* mys = &se[t * 33];
        ull* own = s ? o1 : o0;     // my edge (e0+s == ge), my k-slice
        float out[32];
#pragma unroll
        for (int j = 0; j < 16; j++) {
            float lo, hi; upk(own[j], lo, hi);
            out[2 * j]     = lo + mys[2 * j]     + sB2[2 * j];
            out[2 * j + 1] = hi + mys[2 * j + 1] + sB2[2 * j + 1];
        }
        if (ge < E) {
            float4* eo = (float4*)(e_out + (size_t)ge * 32);
            int dstm = s ? dst1 : dst0;
            float* ag = agg + (size_t)dstm * 32;
#pragma unroll
            for (int c = 0; c < 8; c++) {
                eo[c] = make_float4(out[4 * c], out[4 * c + 1], out[4 * c + 2], out[4 * c + 3]);
                red_add_v4(ag + 4 * c, out[4 * c], out[4 * c + 1], out[4 * c + 2], out[4 * c + 3]);
            }
        }
    }
}

// Node model (baseline form): x_new = relu([x, agg*invdeg, u[batch]]@W1+b1)@W2+b2
__global__ __launch_bounds__(128) void k_node(
    float* __restrict__ x, const float* __restrict__ agg, const float* __restrict__ invdeg,
    const float* __restrict__ u, const int* __restrict__ batch, float* __restrict__ xg,
    const float* __restrict__ W1, const float* __restrict__ b1,
    const float* __restrict__ W2, const float* __restrict__ b2, int N) {
    __shared__ __align__(16) float sW1[96 * 64];
    __shared__ __align__(16) float sW2[64 * 32];
    __shared__ __align__(16) float sB1[64];
    __shared__ __align__(16) float sB2[32];
    for (int i = threadIdx.x; i < 6144; i += 128) sW1[i] = W1[i];
    for (int i = threadIdx.x; i < 2048; i += 128) sW2[i] = W2[i];
    if (threadIdx.x < 64) sB1[threadIdx.x] = b1[threadIdx.x];
    if (threadIdx.x < 32) sB2[threadIdx.x] = b2[threadIdx.x];
    __syncthreads();

    int n = blockIdx.x * blockDim.x + threadIdx.x;
    if (n >= N) return;

    ull h[32];
    const ulonglong2* bb1 = (const ulonglong2*)sB1;
#pragma unroll
    for (int j = 0; j < 16; j++) { ulonglong2 t = bb1[j]; h[2 * j] = t.x; h[2 * j + 1] = t.y; }

    const float4* xp = (const float4*)(x + (size_t)n * 32);
#pragma unroll
    for (int kk = 0; kk < 8; kk++) {
        float4 v = xp[kk];
        mac_row64(h, v.x, sW1 + (4 * kk + 0) * 64);
        mac_row64(h, v.y, sW1 + (4 * kk + 1) * 64);
        mac_row64(h, v.z, sW1 + (4 * kk + 2) * 64);
        mac_row64(h, v.w, sW1 + (4 * kk + 3) * 64);
    }
    float idg = invdeg[n];
    const float4* ap = (const float4*)(agg + (size_t)n * 32);
#pragma unroll
    for (int kk = 0; kk < 8; kk++) {
        float4 v = ap[kk];
        mac_row64(h, v.x * idg, sW1 + (32 + 4 * kk + 0) * 64);
        mac_row64(h, v.y * idg, sW1 + (32 + 4 * kk + 1) * 64);
        mac_row64(h, v.z * idg, sW1 + (32 + 4 * kk + 2) * 64);
        mac_row64(h, v.w * idg, sW1 + (32 + 4 * kk + 3) * 64);
    }
    int b = batch[n];
    const float4* up = (const float4*)(u + (size_t)b * 32);
#pragma unroll
    for (int kk = 0; kk < 8; kk++) {
        float4 v = up[kk];
        mac_row64(h, v.x, sW1 + (64 + 4 * kk + 0) * 64);
        mac_row64(h, v.y, sW1 + (64 + 4 * kk + 1) * 64);
        mac_row64(h, v.z, sW1 + (64 + 4 * kk + 2) * 64);
        mac_row64(h, v.w, sW1 + (64 + 4 * kk + 3) * 64);
    }
#pragma unroll
    for (int j = 0; j < 32; j++) {
        float lo, hi; upk(h[j], lo, hi);
        h[j] = pk(fmaxf(lo, 0.f), fmaxf(hi, 0.f));
    }
    ull o[16];
    const ulonglong2* bb2 = (const ulonglong2*)sB2;
#pragma unroll
    for (int j = 0; j < 8; j++) { ulonglong2 t = bb2[j]; o[2 * j] = t.x; o[2 * j + 1] = t.y; }
#pragma unroll
    for (int kp = 0; kp < 32; kp++) {
        float lo, hi; upk(h[kp], lo, hi);
        mac_row32(o, lo, sW2 + (2 * kp) * 32);
        mac_row32(o, hi, sW2 + (2 * kp + 1) * 32);
    }
    float f[32];
#pragma unroll
    for (int j = 0; j < 16; j++) upk(o[j], f[2 * j], f[2 * j + 1]);

    float4* xo = (float4*)(x + (size_t)n * 32);
#pragma unroll
    for (int c = 0; c < 8; c++) xo[c] = make_float4(f[4 * c], f[4 * c + 1], f[4 * c + 2], f[4 * c + 3]);
    float* gp = xg + (size_t)b * 32;
#pragma unroll
    for (int c = 0; c < 8; c++) red_add_v4(gp + 4 * c, f[4 * c], f[4 * c + 1], f[4 * c + 2], f[4 * c + 3]);
}

__global__ void k_glob(float* __restrict__ u, const float* __restrict__ xg,
                       const float* __restrict__ invgc,
                       const float* __restrict__ W1, const float* __restrict__ b1,
                       const float* __restrict__ W2, const float* __restrict__ b2, int B) {
    __shared__ float sh[BMAX * 64];
    int t = threadIdx.x;
    {
        int b = t >> 6, j = t & 63;
        if (b < B) {
            float acc = b1[j];
            float ig = invgc[b];
#pragma unroll
            for (int k = 0; k < 32; k++) acc += u[b * 32 + k] * W1[k * 64 + j];
#pragma unroll
            for (int k = 0; k < 32; k++) acc += xg[b * 32 + k] * ig * W1[(32 + k) * 64 + j];
            sh[b * 64 + j] = fmaxf(acc, 0.f);
        }
    }
    __syncthreads();
    {
        int b = t >> 5, jo = t & 31;
        if (t < B * 32) {
            float acc = b2[jo];
#pragma unroll
            for (int k = 0; k < 64; k++) acc += sh[b * 64 + k] * W2[k * 32 + jo];
            u[b * 32 + jo] = acc;
        }
    }
}

// ---------------- launch ----------------
extern "C" void kernel_launch(void* const* d_in, const int* in_sizes, int n_in,
                              void* d_out, int out_size) {
    const float* node_feats = (const float*)d_in[0];
    const int*   edge_index = (const int*)d_in[1];
    const float* edge_feats = (const float*)d_in[2];
    const float* glob_feats = (const float*)d_in[3];
    const int*   batch      = (const int*)d_in[4];
    const float* node_gamma = (const float*)d_in[5];
    const float* node_beta  = (const float*)d_in[6];
    const float* edge_gamma = (const float*)d_in[7];
    const float* edge_beta  = (const float*)d_in[8];
    const float* glob_gamma = (const float*)d_in[9];
    const float* glob_beta  = (const float*)d_in[10];
    const float* edge_W1 = (const float*)d_in[11];
    const float* edge_b1 = (const float*)d_in[12];
    const float* edge_W2 = (const float*)d_in[13];
    const float* edge_b2 = (const float*)d_in[14];
    const float* node_W1 = (const float*)d_in[15];
    const float* node_b1 = (const float*)d_in[16];
    const float* node_W2 = (const float*)d_in[17];
    const float* node_b2 = (const float*)d_in[18];
    const float* glob_W1 = (const float*)d_in[19];
    const float* glob_b1 = (const float*)d_in[20];
    const float* glob_W2 = (const float*)d_in[21];
    const float* glob_b2 = (const float*)d_in[22];

    const int N = in_sizes[0] / D32;
    const int E = in_sizes[2] / D32;
    const int B = in_sizes[3] / D32;

    float* x = (float*)d_out;
    float* e = x + (size_t)N * D32;
    float* u = e + (size_t)E * D32;

    void *pPQ, *pR, *pAgg, *pXg, *pInvdeg, *pInvgc, *pDeg, *pGcnt;
    cudaGetSymbolAddress(&pPQ, g_PQ);
    cudaGetSymbolAddress(&pR, g_R);
    cudaGetSymbolAddress(&pAgg, g_agg);
    cudaGetSymbolAddress(&pXg, g_xg);
    cudaGetSymbolAddress(&pInvdeg, g_invdeg);
    cudaGetSymbolAddress(&pInvgc, g_invgc);
    cudaGetSymbolAddress(&pDeg, g_deg);
    cudaGetSymbolAddress(&pGcnt, g_gcnt);

    // 0: BN(x) + zero deg    1: BN(u) + zero gcnt
    k_bn<<<(N * 8 + 255) / 256, 256>>>((const float4*)node_feats, (float4*)x,
                                       node_gamma, node_beta, N * 8, (int*)pDeg, N);
    k_bn<<<1, 256>>>((const float4*)glob_feats, (float4*)u,
                     glob_gamma, glob_beta, B * 8, (int*)pGcnt, B);

    for (int l = 0; l < 3; l++) {
        const float* eW1 = edge_W1 + (size_t)l * 128 * 64;
        // 2: k_pq (+zero agg)   3: k_r (+zero xg)
        k_pq<<<(N + 3) / 4, 256>>>(x, eW1, (float*)pPQ, (float*)pAgg, N);
        k_r<<<1, 1024>>>(u, eW1, edge_b1 + l * 64, (float*)pR, (float*)pXg, B);
        if (l == 0) {
            // 4: deg count (needed only before k_node) — makes k_edge2 launch #5
            k_count<<<(E + 255) / 256, 256>>>(edge_index + E, (int*)pDeg, E);
        }
        // 5 (layer 0): the hot kernel — ncu -s 5 lands here
        k_edge2<<<(E + 127) / 128, 128>>>((const float*)pPQ, (const float*)pR,
                                          edge_index, batch,
                                          (l == 0) ? edge_feats : e, e,
                                          (float*)pAgg,
                                          eW1 + 64 * 64, edge_W2 + (size_t)l * 2048,
                                          edge_b2 + l * 32,
                                          edge_gamma, edge_beta, (l == 0) ? 1 : 0, E);
        if (l == 0) {
            k_count<<<(N + 255) / 256, 256>>>(batch, (int*)pGcnt, N);
            k_inv<<<(N + 255) / 256, 256>>>((const int*)pDeg, (float*)pInvdeg, N,
                                            (const int*)pGcnt, (float*)pInvgc, B);
        }
        k_node<<<(N + 127) / 128, 128>>>(x, (const float*)pAgg, (const float*)pInvdeg,
                                         u, batch, (float*)pXg,
                                         node_W1 + (size_t)l * 6144, node_b1 + l * 64,
                                         node_W2 + (size_t)l * 2048, node_b2 + l * 32, N);
        k_glob<<<1, 1024>>>(u, (const float*)pXg, (const float*)pInvgc,
                            glob_W1 + (size_t)l * 4096, glob_b1 + l * 64,
                            glob_W2 + (size_t)l * 2048, glob_b2 + l * 32, B);
    }
}